// round 8
// baseline (speedup 1.0000x reference)
#include <cuda_runtime.h>
#include <math.h>
#include <stdint.h>

// ---------------------------------------------------------------------------
// GNN_16535624089969: 2-layer GCN (DGL GraphConv norm='both')
//   N=50000, E=800000, dims 256 -> 128 -> 64, fp32.
// R7: - GEMM2 -> mma.sync bf16 3-split too (A pre-split by agg1, W pre-split
//       by wconv); GEMM1 B-tile now loads pre-split W1 (no per-CTA cvt).
//     - agg1 emits hs2 as bf16 hi/lo (exact to 2^-16, same write bytes).
//     - agg1 / GEMM2 pipelined in two node-halves across the fork streams.
// ---------------------------------------------------------------------------

#define MAXN 50048
#define MAXE 800000
#define IN_DIM 256
#define HID_DIM 128
#define OUT_DIM 64
#define SCAN_BLK 1024
#define MAX_SCAN_BLOCKS 64
#define SROW 36

__device__ float g_h1[50000 * HID_DIM];            // x@W1 (no norm)
__device__ unsigned short g_hs2h[50000 * HID_DIM]; // hs2 bf16 hi
__device__ unsigned short g_hs2l[50000 * HID_DIM]; // hs2 bf16 lo
__device__ float g_g2 [50000 * OUT_DIM];           // hs2 @ W2
__device__ unsigned short g_W1th[HID_DIM * IN_DIM];  // W1^T bf16 hi [n][k]
__device__ unsigned short g_W1tl[HID_DIM * IN_DIM];  // W1^T bf16 lo
__device__ unsigned short g_W2th[OUT_DIM * HID_DIM]; // W2^T bf16 hi [n][k]
__device__ unsigned short g_W2tl[OUT_DIM * HID_DIM]; // W2^T bf16 lo
__device__ int   g_csr_src[MAXE];
__device__ int   g_row_ptr[MAXN + 1];
__device__ int   g_cursor[MAXN];
__device__ int   g_outdeg[MAXN];
__device__ int   g_indeg[MAXN];
__device__ float g_ns[MAXN];
__device__ float g_nd[MAXN];
__device__ int   g_block_sums[MAX_SCAN_BLOCKS];

// ---------------------------------------------------------------------------
// helpers
// ---------------------------------------------------------------------------
__device__ __forceinline__ void splitbf(float v, unsigned short& h,
                                        unsigned short& l) {
    unsigned short hh;
    float hf;
    asm("cvt.rn.bf16.f32 %0, %1;" : "=h"(hh) : "f"(v));
    asm("mov.b32 %0, {0, %1};" : "=f"(hf) : "h"(hh));
    float r = v - hf;
    unsigned short ll;
    asm("cvt.rn.bf16.f32 %0, %1;" : "=h"(ll) : "f"(r));
    h = hh; l = ll;
}

__device__ __forceinline__ void mma16816(float* c, const uint32_t* a,
                                         const uint32_t* b) {
    asm volatile(
        "mma.sync.aligned.m16n8k16.row.col.f32.bf16.bf16.f32 "
        "{%0,%1,%2,%3}, {%4,%5,%6,%7}, {%8,%9}, {%0,%1,%2,%3};"
        : "+f"(c[0]), "+f"(c[1]), "+f"(c[2]), "+f"(c[3])
        : "r"(a[0]), "r"(a[1]), "r"(a[2]), "r"(a[3]), "r"(b[0]), "r"(b[1]));
}

// ---------------------------------------------------------------------------
// graph-structure kernels
// ---------------------------------------------------------------------------
__global__ void zero_kernel(int n) {
    int i = blockIdx.x * blockDim.x + threadIdx.x;
    if (i < n) { g_outdeg[i] = 0; g_indeg[i] = 0; g_cursor[i] = 0; }
}

__global__ void deg_kernel(const int* __restrict__ src,
                           const int* __restrict__ dst, int E) {
    int e = blockIdx.x * blockDim.x + threadIdx.x;
    if (e < E) {
        atomicAdd(&g_outdeg[src[e]], 1);
        atomicAdd(&g_indeg[dst[e]], 1);
    }
}

__global__ __launch_bounds__(SCAN_BLK)
void scan1_kernel(int n) {
    int tid = threadIdx.x, i = blockIdx.x * SCAN_BLK + tid;
    int lane = tid & 31, w = tid >> 5;
    if (blockIdx.x == 0 && tid == 0) g_row_ptr[0] = 0;
    int indeg = 0;
    if (i < n) {
        indeg = g_indeg[i];
        g_ns[i] = rsqrtf(fmaxf((float)g_outdeg[i], 1.0f));
        g_nd[i] = rsqrtf(fmaxf((float)indeg, 1.0f));
    }
    int s = indeg;
#pragma unroll
    for (int d = 1; d < 32; d <<= 1) {
        int t = __shfl_up_sync(0xffffffffu, s, d);
        if (lane >= d) s += t;
    }
    __shared__ int wsum[32];
    if (lane == 31) wsum[w] = s;
    __syncthreads();
    if (w == 0) {
        int x = wsum[lane];
#pragma unroll
        for (int d = 1; d < 32; d <<= 1) {
            int t = __shfl_up_sync(0xffffffffu, x, d);
            if (lane >= d) x += t;
        }
        wsum[lane] = x;
    }
    __syncthreads();
    if (w > 0) s += wsum[w - 1];
    if (i < n) g_row_ptr[i + 1] = s;
    if (tid == SCAN_BLK - 1) g_block_sums[blockIdx.x] = s;
}

__global__ __launch_bounds__(SCAN_BLK)
void scan3_kernel(int n) {
    __shared__ int s_off;
    int bid = blockIdx.x;
    if (threadIdx.x < 32) {
        int acc = 0;
        for (int j = threadIdx.x; j < bid; j += 32) acc += g_block_sums[j];
#pragma unroll
        for (int d = 16; d; d >>= 1) acc += __shfl_down_sync(0xffffffffu, acc, d);
        if (threadIdx.x == 0) s_off = acc;
    }
    __syncthreads();
    int i = bid * SCAN_BLK + threadIdx.x;
    if (i < n) g_row_ptr[i + 1] += s_off;
}

__global__ void csr_fill_kernel(const int* __restrict__ src,
                                const int* __restrict__ dst, int E) {
    int e = blockIdx.x * blockDim.x + threadIdx.x;
    if (e < E) {
        int d = dst[e];
        int pos = g_row_ptr[d] + atomicAdd(&g_cursor[d], 1);
        g_csr_src[pos] = src[e];
    }
}

// ---------------------------------------------------------------------------
// W transpose + bf16 hi/lo split (runs once, on the side stream, ~2us)
// ---------------------------------------------------------------------------
__global__ void wconv_kernel(const float* __restrict__ W1,
                             const float* __restrict__ W2) {
    int i = blockIdx.x * blockDim.x + threadIdx.x;
    if (i < HID_DIM * IN_DIM) {
        int nn = i / IN_DIM, k = i % IN_DIM;
        unsigned short h, l;
        splitbf(W1[k * HID_DIM + nn], h, l);
        g_W1th[i] = h; g_W1tl[i] = l;
    }
    if (i < OUT_DIM * HID_DIM) {
        int nn = i / HID_DIM, k = i % HID_DIM;
        unsigned short h, l;
        splitbf(W2[k * OUT_DIM + nn], h, l);
        g_W2th[i] = h; g_W2tl[i] = l;
    }
}

// ---------------------------------------------------------------------------
// GEMM1: C[M,128] = A[M,256] @ W1, mma.sync bf16 3-split.
// A fp32, split in-kernel; B pre-split (g_W1th/l, [n][k] layout).
// ---------------------------------------------------------------------------
__global__ __launch_bounds__(256)
void gemm1_mma_kernel(const float* __restrict__ A, float* __restrict__ C,
                      int M) {
    __shared__ __align__(16) unsigned short sAh[128 * SROW];
    __shared__ __align__(16) unsigned short sAl[128 * SROW];
    __shared__ __align__(16) unsigned short sBh[128 * SROW];
    __shared__ __align__(16) unsigned short sBl[128 * SROW];

    const int tid = threadIdx.x;
    const int lane = tid & 31, wid = tid >> 5;
    const int g = lane >> 2, t = lane & 3;
    const int warp_m = (wid & 1) * 64;
    const int warp_n = (wid >> 1) * 32;
    const int block_row = blockIdx.x * 128;

    float acc[4][4][4];
#pragma unroll
    for (int i = 0; i < 4; i++)
#pragma unroll
        for (int j = 0; j < 4; j++)
#pragma unroll
            for (int q = 0; q < 4; q++) acc[i][j][q] = 0.0f;

    const int lr = tid >> 1;
    const int lk = tid & 1;

    for (int k0 = 0; k0 < IN_DIM; k0 += 32) {
        // A tile: fp32 -> bf16 hi/lo
        {
            int grow = block_row + lr;
            float v[16];
            if (grow < M) {
                const float4* ap =
                    (const float4*)&A[(size_t)grow * IN_DIM + k0 + lk * 16];
#pragma unroll
                for (int j = 0; j < 4; j++) {
                    float4 f = ap[j];
                    v[j * 4 + 0] = f.x; v[j * 4 + 1] = f.y;
                    v[j * 4 + 2] = f.z; v[j * 4 + 3] = f.w;
                }
            } else {
#pragma unroll
                for (int j = 0; j < 16; j++) v[j] = 0.0f;
            }
            unsigned short h[16], l[16];
#pragma unroll
            for (int j = 0; j < 16; j++) splitbf(v[j], h[j], l[j]);
            int base = lr * SROW + lk * 16;
#pragma unroll
            for (int j = 0; j < 4; j++) {
                *(uint2*)&sAh[base + j * 4] = make_uint2(
                    (uint32_t)h[j*4+0] | ((uint32_t)h[j*4+1] << 16),
                    (uint32_t)h[j*4+2] | ((uint32_t)h[j*4+3] << 16));
                *(uint2*)&sAl[base + j * 4] = make_uint2(
                    (uint32_t)l[j*4+0] | ((uint32_t)l[j*4+1] << 16),
                    (uint32_t)l[j*4+2] | ((uint32_t)l[j*4+3] << 16));
            }
        }
        // B tile: pure bf16 copy from pre-split W1t
        {
            int sbase = lr * SROW + lk * 16;
            int gbase = lr * IN_DIM + k0 + lk * 16;
#pragma unroll
            for (int j = 0; j < 4; j++) {
                *(uint2*)&sBh[sbase + j * 4] =
                    *(const uint2*)&g_W1th[gbase + j * 4];
                *(uint2*)&sBl[sbase + j * 4] =
                    *(const uint2*)&g_W1tl[gbase + j * 4];
            }
        }
        __syncthreads();

#pragma unroll
        for (int kk = 0; kk < 32; kk += 16) {
            uint32_t ah[4][4], al[4][4];
#pragma unroll
            for (int mt = 0; mt < 4; mt++) {
                int row = warp_m + mt * 16 + g;
                int b0 = row * SROW + kk + 2 * t;
                ah[mt][0] = *(const uint32_t*)&sAh[b0];
                ah[mt][1] = *(const uint32_t*)&sAh[b0 + 8 * SROW];
                ah[mt][2] = *(const uint32_t*)&sAh[b0 + 8];
                ah[mt][3] = *(const uint32_t*)&sAh[b0 + 8 * SROW + 8];
                al[mt][0] = *(const uint32_t*)&sAl[b0];
                al[mt][1] = *(const uint32_t*)&sAl[b0 + 8 * SROW];
                al[mt][2] = *(const uint32_t*)&sAl[b0 + 8];
                al[mt][3] = *(const uint32_t*)&sAl[b0 + 8 * SROW + 8];
            }
            uint32_t bh[4][2], bl[4][2];
#pragma unroll
            for (int nt = 0; nt < 4; nt++) {
                int nr = warp_n + nt * 8 + g;
                int b0 = nr * SROW + kk + 2 * t;
                bh[nt][0] = *(const uint32_t*)&sBh[b0];
                bh[nt][1] = *(const uint32_t*)&sBh[b0 + 8];
                bl[nt][0] = *(const uint32_t*)&sBl[b0];
                bl[nt][1] = *(const uint32_t*)&sBl[b0 + 8];
            }
#pragma unroll
            for (int mt = 0; mt < 4; mt++)
#pragma unroll
                for (int nt = 0; nt < 4; nt++) {
                    mma16816(acc[mt][nt], ah[mt], bh[nt]);
                    mma16816(acc[mt][nt], al[mt], bh[nt]);
                    mma16816(acc[mt][nt], ah[mt], bl[nt]);
                }
        }
        __syncthreads();
    }

#pragma unroll
    for (int mt = 0; mt < 4; mt++) {
        int row = block_row + warp_m + mt * 16 + g;
#pragma unroll
        for (int nt = 0; nt < 4; nt++) {
            int col = warp_n + nt * 8 + 2 * t;
            if (row < M)
                *(float2*)&C[(size_t)row * HID_DIM + col] =
                    make_float2(acc[mt][nt][0], acc[mt][nt][1]);
            if (row + 8 < M)
                *(float2*)&C[(size_t)(row + 8) * HID_DIM + col] =
                    make_float2(acc[mt][nt][2], acc[mt][nt][3]);
        }
    }
}

// ---------------------------------------------------------------------------
// GEMM2: g2[rows,64] = hs2[rows,128] @ W2, mma.sync bf16 3-split.
// A pre-split by agg1 (g_hs2h/l), B pre-split (g_W2th/l).
// CTA tile 128x64; warps: warp_m {0,64}, warp_n {0,16,32,48}; mt 4, nt 2.
// ---------------------------------------------------------------------------
__global__ __launch_bounds__(256)
void gemm2_mma_kernel(float* __restrict__ C, int row_base, int M) {
    __shared__ __align__(16) unsigned short sAh[128 * SROW];
    __shared__ __align__(16) unsigned short sAl[128 * SROW];
    __shared__ __align__(16) unsigned short sBh[64 * SROW];
    __shared__ __align__(16) unsigned short sBl[64 * SROW];

    const int tid = threadIdx.x;
    const int lane = tid & 31, wid = tid >> 5;
    const int g = lane >> 2, t = lane & 3;
    const int warp_m = (wid & 1) * 64;
    const int warp_n = (wid >> 1) * 16;
    const int block_row = row_base + blockIdx.x * 128;

    float acc[4][2][4];
#pragma unroll
    for (int i = 0; i < 4; i++)
#pragma unroll
        for (int j = 0; j < 2; j++)
#pragma unroll
            for (int q = 0; q < 4; q++) acc[i][j][q] = 0.0f;

    const int lr = tid >> 1;      // 0..127
    const int lk = tid & 1;
    const int br = tid >> 2;      // 0..63
    const int bq = tid & 3;       // 8 k each

    for (int k0 = 0; k0 < HID_DIM; k0 += 32) {
        // A tile: bf16 copy from pre-split hs2
        {
            int grow = block_row + lr;
            int sbase = lr * SROW + lk * 16;
            if (grow < M) {
                size_t gbase = (size_t)grow * HID_DIM + k0 + lk * 16;
#pragma unroll
                for (int j = 0; j < 4; j++) {
                    *(uint2*)&sAh[sbase + j * 4] =
                        *(const uint2*)&g_hs2h[gbase + j * 4];
                    *(uint2*)&sAl[sbase + j * 4] =
                        *(const uint2*)&g_hs2l[gbase + j * 4];
                }
            } else {
#pragma unroll
                for (int j = 0; j < 4; j++) {
                    *(uint2*)&sAh[sbase + j * 4] = make_uint2(0u, 0u);
                    *(uint2*)&sAl[sbase + j * 4] = make_uint2(0u, 0u);
                }
            }
        }
        // B tile: bf16 copy from pre-split W2t
        {
            int sbase = br * SROW + bq * 8;
            int gbase = br * HID_DIM + k0 + bq * 8;
#pragma unroll
            for (int j = 0; j < 2; j++) {
                *(uint2*)&sBh[sbase + j * 4] =
                    *(const uint2*)&g_W2th[gbase + j * 4];
                *(uint2*)&sBl[sbase + j * 4] =
                    *(const uint2*)&g_W2tl[gbase + j * 4];
            }
        }
        __syncthreads();

#pragma unroll
        for (int kk = 0; kk < 32; kk += 16) {
            uint32_t ah[4][4], al[4][4];
#pragma unroll
            for (int mt = 0; mt < 4; mt++) {
                int row = warp_m + mt * 16 + g;
                int b0 = row * SROW + kk + 2 * t;
                ah[mt][0] = *(const uint32_t*)&sAh[b0];
                ah[mt][1] = *(const uint32_t*)&sAh[b0 + 8 * SROW];
                ah[mt][2] = *(const uint32_t*)&sAh[b0 + 8];
                ah[mt][3] = *(const uint32_t*)&sAh[b0 + 8 * SROW + 8];
                al[mt][0] = *(const uint32_t*)&sAl[b0];
                al[mt][1] = *(const uint32_t*)&sAl[b0 + 8 * SROW];
                al[mt][2] = *(const uint32_t*)&sAl[b0 + 8];
                al[mt][3] = *(const uint32_t*)&sAl[b0 + 8 * SROW + 8];
            }
            uint32_t bh[2][2], bl[2][2];
#pragma unroll
            for (int nt = 0; nt < 2; nt++) {
                int nr = warp_n + nt * 8 + g;
                int b0 = nr * SROW + kk + 2 * t;
                bh[nt][0] = *(const uint32_t*)&sBh[b0];
                bh[nt][1] = *(const uint32_t*)&sBh[b0 + 8];
                bl[nt][0] = *(const uint32_t*)&sBl[b0];
                bl[nt][1] = *(const uint32_t*)&sBl[b0 + 8];
            }
#pragma unroll
            for (int mt = 0; mt < 4; mt++)
#pragma unroll
                for (int nt = 0; nt < 2; nt++) {
                    mma16816(acc[mt][nt], ah[mt], bh[nt]);
                    mma16816(acc[mt][nt], al[mt], bh[nt]);
                    mma16816(acc[mt][nt], ah[mt], bl[nt]);
                }
        }
        __syncthreads();
    }

#pragma unroll
    for (int mt = 0; mt < 4; mt++) {
        int row = block_row + warp_m + mt * 16 + g;
#pragma unroll
        for (int nt = 0; nt < 2; nt++) {
            int col = warp_n + nt * 8 + 2 * t;
            if (row < M)
                *(float2*)&C[(size_t)row * OUT_DIM + col] =
                    make_float2(acc[mt][nt][0], acc[mt][nt][1]);
            if (row + 8 < M)
                *(float2*)&C[(size_t)(row + 8) * OUT_DIM + col] =
                    make_float2(acc[mt][nt][2], acc[mt][nt][3]);
        }
    }
}

// ---------------------------------------------------------------------------
// Layer-1 aggregation over [node_lo, node_hi); emits hs2 as bf16 hi/lo.
// ---------------------------------------------------------------------------
__global__ __launch_bounds__(256)
void agg1_kernel(const float* __restrict__ b1, int node_lo, int node_hi) {
    int node = node_lo + blockIdx.x * (blockDim.x >> 5) + (threadIdx.x >> 5);
    if (node >= node_hi) return;
    int lane = threadIdx.x & 31;
    int s = g_row_ptr[node], e = g_row_ptr[node + 1];
    float4 acc = make_float4(0.f, 0.f, 0.f, 0.f);
#pragma unroll 4
    for (int j = s; j < e; j++) {
        int u = g_csr_src[j];
        float nsu = __ldg(&g_ns[u]);
        float4 v = *(const float4*)&g_h1[(size_t)u * HID_DIM + lane * 4];
        acc.x = fmaf(v.x, nsu, acc.x);
        acc.y = fmaf(v.y, nsu, acc.y);
        acc.z = fmaf(v.z, nsu, acc.z);
        acc.w = fmaf(v.w, nsu, acc.w);
    }
    float nd = g_nd[node], ns = g_ns[node];
    float4 bb = *(const float4*)&b1[lane * 4];
    float o[4];
    o[0] = fmaxf(fmaf(acc.x, nd, bb.x), 0.f) * ns;
    o[1] = fmaxf(fmaf(acc.y, nd, bb.y), 0.f) * ns;
    o[2] = fmaxf(fmaf(acc.z, nd, bb.z), 0.f) * ns;
    o[3] = fmaxf(fmaf(acc.w, nd, bb.w), 0.f) * ns;
    unsigned short h[4], l[4];
#pragma unroll
    for (int q = 0; q < 4; q++) splitbf(o[q], h[q], l[q]);
    size_t base = (size_t)node * HID_DIM + lane * 4;
    *(uint2*)&g_hs2h[base] = make_uint2(
        (uint32_t)h[0] | ((uint32_t)h[1] << 16),
        (uint32_t)h[2] | ((uint32_t)h[3] << 16));
    *(uint2*)&g_hs2l[base] = make_uint2(
        (uint32_t)l[0] | ((uint32_t)l[1] << 16),
        (uint32_t)l[2] | ((uint32_t)l[3] << 16));
}

// ---------------------------------------------------------------------------
// Layer-2 aggregation
// ---------------------------------------------------------------------------
__global__ __launch_bounds__(256)
void agg2_kernel(const float* __restrict__ b2, float* __restrict__ out, int n) {
    int node = blockIdx.x * (blockDim.x >> 5) + (threadIdx.x >> 5);
    if (node >= n) return;
    int lane = threadIdx.x & 31;
    int s = g_row_ptr[node], e = g_row_ptr[node + 1];
    float2 acc = make_float2(0.f, 0.f);
#pragma unroll 4
    for (int j = s; j < e; j++) {
        int u = g_csr_src[j];
        float2 v = *(const float2*)&g_g2[(size_t)u * OUT_DIM + lane * 2];
        acc.x += v.x; acc.y += v.y;
    }
    float nd = g_nd[node];
    float2 bb = *(const float2*)&b2[lane * 2];
    float2 o;
    o.x = fmaf(acc.x, nd, bb.x);
    o.y = fmaf(acc.y, nd, bb.y);
    *(float2*)&out[(size_t)node * OUT_DIM + lane * 2] = o;
}

// ---------------------------------------------------------------------------
extern "C" void kernel_launch(void* const* d_in, const int* in_sizes, int n_in,
                              void* d_out, int out_size) {
    const float* x   = (const float*)d_in[0];
    const float* W1  = (const float*)d_in[1];
    const float* b1  = (const float*)d_in[2];
    const float* W2  = (const float*)d_in[3];
    const float* b2  = (const float*)d_in[4];
    const int*   src = (const int*)d_in[5];
    const int*   dst = (const int*)d_in[6];
    float* out = (float*)d_out;

    const int n = in_sizes[0] / IN_DIM;      // 50000
    const int E = in_sizes[5];               // 800000

    float *p_h1, *p_g2;
    cudaGetSymbolAddress((void**)&p_h1, g_h1);
    cudaGetSymbolAddress((void**)&p_g2, g_g2);

    const int nscan = (n + SCAN_BLK - 1) / SCAN_BLK;

    cudaStream_t s2;
    cudaStreamCreate(&s2);
    cudaEvent_t e_fork, e_join, eA0, eG0;
    cudaEventCreateWithFlags(&e_fork, cudaEventDisableTiming);
    cudaEventCreateWithFlags(&e_join, cudaEventDisableTiming);
    cudaEventCreateWithFlags(&eA0, cudaEventDisableTiming);
    cudaEventCreateWithFlags(&eG0, cudaEventDisableTiming);

    cudaEventRecord(e_fork, 0);
    cudaStreamWaitEvent(s2, e_fork, 0);

    // side stream: W split, then GEMM1 (independent of graph structure)
    wconv_kernel<<<(HID_DIM * IN_DIM + 255) / 256, 256, 0, s2>>>(W1, W2);
    gemm1_mma_kernel<<<(n + 127) / 128, 256, 0, s2>>>(x, p_h1, n);
    cudaEventRecord(e_join, s2);

    // main stream: graph structure
    zero_kernel<<<(n + 255) / 256, 256>>>(n);
    deg_kernel<<<(E + 255) / 256, 256>>>(src, dst, E);
    scan1_kernel<<<nscan, SCAN_BLK>>>(n);
    scan3_kernel<<<nscan, SCAN_BLK>>>(n);
    csr_fill_kernel<<<(E + 255) / 256, 256>>>(src, dst, E);

    cudaStreamWaitEvent(0, e_join, 0);

    // pipelined tail: agg1(h0) -> [gemm2(h0) on s2 || agg1(h1)] -> gemm2(h1)
    const int half = ((n / 2) + 127) & ~127;             // multiple of 128
    agg1_kernel<<<(half + 7) / 8, 256>>>(b1, 0, half);
    cudaEventRecord(eA0, 0);
    agg1_kernel<<<(n - half + 7) / 8, 256>>>(b1, half, n);

    cudaStreamWaitEvent(s2, eA0, 0);
    gemm2_mma_kernel<<<half / 128, 256, 0, s2>>>(p_g2, 0, n);
    cudaEventRecord(eG0, s2);

    gemm2_mma_kernel<<<(n - half + 127) / 128, 256>>>(p_g2, half, n);
    cudaStreamWaitEvent(0, eG0, 0);

    agg2_kernel<<<(n + 7) / 8, 256>>>(b2, out, n);
}